// round 6
// baseline (speedup 1.0000x reference)
#include <cuda_runtime.h>
#include <cuda_bf16.h>
#include <cstdint>

#define IN_DIM   1024
#define OUT_DIM  512
#define BATCH    1024
#define K2       2048           // interleaved K dimension (2 terms per input)
#define BM       64             // batch rows per CTA
#define BN       32             // out cols per CTA
#define BK       64             // bf16 k per smem stage (= 128B per row)
#define NITER    (K2 / BK)      // 32 K-stages; each 8-warp group does 16
#define ROW_B    128            // smem row stride (XOR swizzle, no padding)
#define A_TILE   (BM * ROW_B)   // 8192
#define B_TILE   (BN * ROW_B)   // 4096
#define STAGE_B  (A_TILE + B_TILE)          // 12288
#define NSLOT    6                           // 3 slots per K-group
#define EXCH_OFF (NSLOT * STAGE_B)           // 73728
#define SMEM_TOT (EXCH_OFF + 128 * 64)       // + 8KB acc exchange = 81920

// ---------------- static scratch (no allocs allowed) ----------------
__device__ float          g_c[OUT_DIM];                    // exact fp32 c[o]
__device__ __nv_bfloat16  g_H[(size_t)BATCH  * K2];        // (x^2, x) interleaved
__device__ __nv_bfloat16  g_G[(size_t)OUT_DIM * K2];       // (u^2, -2u^2 w) interleaved

// ---------------- PTX helpers (baseline PTX only: sm_80-class ops) ----------
__device__ __forceinline__ uint32_t smem_u32(const void* p) {
    uint32_t a;
    asm("{ .reg .u64 t; cvta.to.shared.u64 t, %1; cvt.u32.u64 %0, t; }" : "=r"(a) : "l"(p));
    return a;
}
__device__ __forceinline__ void cp_async16(uint32_t dst, const void* src) {
    asm volatile("cp.async.cg.shared.global [%0], [%1], 16;" :: "r"(dst), "l"(src) : "memory");
}
#define CP_COMMIT()  asm volatile("cp.async.commit_group;" ::: "memory")
#define CP_WAIT(n)   asm volatile("cp.async.wait_group %0;" :: "n"(n) : "memory")
#define BAR_SYNC(id, cnt) \
    asm volatile("bar.sync %0, %1;" :: "r"(id), "r"(cnt) : "memory")

__device__ __forceinline__ void ldsm_x4(uint32_t& r0, uint32_t& r1, uint32_t& r2, uint32_t& r3,
                                        uint32_t addr) {
    asm volatile("ldmatrix.sync.aligned.m8n8.x4.shared.b16 {%0,%1,%2,%3}, [%4];"
                 : "=r"(r0), "=r"(r1), "=r"(r2), "=r"(r3) : "r"(addr));
}
__device__ __forceinline__ void mma16816(float* c, const uint32_t* a, const uint32_t* b) {
    asm volatile(
        "mma.sync.aligned.m16n8k16.row.col.f32.bf16.bf16.f32 "
        "{%0,%1,%2,%3}, {%4,%5,%6,%7}, {%8,%9}, {%0,%1,%2,%3};"
        : "+f"(c[0]), "+f"(c[1]), "+f"(c[2]), "+f"(c[3])
        : "r"(a[0]), "r"(a[1]), "r"(a[2]), "r"(a[3]), "r"(b[0]), "r"(b[1]));
}

__device__ __forceinline__ float pack_bf2(float hi_from_lo, float lo) {
    __nv_bfloat162 t = __nv_bfloat162(__float2bfloat16_rn(hi_from_lo), __float2bfloat16_rn(lo));
    return __uint_as_float(*(uint32_t*)&t);
}

// ---------------------------------------------------------------------------
// Fused prep (one launch):
//   blocks [0,256):   H[b, 2i]=bf16(x^2), H[b, 2i+1]=bf16(x)     MLP=4
//   blocks [256,768): G[o, 2i]=bf16(u^2), G[o, 2i+1]=bf16(-2u^2w)
//                     + exact fp32 c[o] = sum (u w)^2
// ---------------------------------------------------------------------------
__global__ __launch_bounds__(256) void prep_all_kernel(const float* __restrict__ x,
                                                       const float* __restrict__ w,
                                                       const float* __restrict__ u) {
    const int t = threadIdx.x;
    if (blockIdx.x < 256) {
        const int base = blockIdx.x * 1024;       // float4 index base (4 per thread)
        float4 v[4];
        #pragma unroll
        for (int j = 0; j < 4; j++)               // batch the 4 loads -> MLP=4
            v[j] = reinterpret_cast<const float4*>(x)[base + t + j * 256];
        #pragma unroll
        for (int j = 0; j < 4; j++) {
            float4 p;
            p.x = pack_bf2(v[j].x * v[j].x, v[j].x);
            p.y = pack_bf2(v[j].y * v[j].y, v[j].y);
            p.z = pack_bf2(v[j].z * v[j].z, v[j].z);
            p.w = pack_bf2(v[j].w * v[j].w, v[j].w);
            reinterpret_cast<float4*>(g_H)[base + t + j * 256] = p;
        }
    } else {
        const int o = blockIdx.x - 256;
        float4 uv = reinterpret_cast<const float4*>(u + (size_t)o * IN_DIM)[t];
        float4 wv = reinterpret_cast<const float4*>(w + (size_t)o * IN_DIM)[t];

        float a0 = uv.x * uv.x, a1 = uv.y * uv.y, a2 = uv.z * uv.z, a3 = uv.w * uv.w;
        float4 p;
        p.x = pack_bf2(a0, -2.f * a0 * wv.x);
        p.y = pack_bf2(a1, -2.f * a1 * wv.y);
        p.z = pack_bf2(a2, -2.f * a2 * wv.z);
        p.w = pack_bf2(a3, -2.f * a3 * wv.w);
        reinterpret_cast<float4*>(g_G + (size_t)o * K2)[t] = p;

        float p0 = uv.x * wv.x, p1 = uv.y * wv.y, p2 = uv.z * wv.z, p3 = uv.w * wv.w;
        float s = fmaf(p0, p0, fmaf(p1, p1, fmaf(p2, p2, p3 * p3)));
        __shared__ float red[256];
        red[t] = s;
        __syncthreads();
        for (int k = 128; k >= 32; k >>= 1) {
            if (t < k) red[t] += red[t + k];
            __syncthreads();
        }
        if (t < 32) {
            float v = red[t];
            #pragma unroll
            for (int off = 16; off > 0; off >>= 1)
                v += __shfl_down_sync(0xffffffffu, v, off);
            if (t == 0) g_c[o] = v;
        }
    }
}

// ---------------------------------------------------------------------------
// Main: bf16 mma.sync dual-GEMM, two independent K-group pipelines per CTA.
// grid = (OUT/32, BATCH/64) = (16, 16) = 256 CTAs, 256 threads (8 warps).
// Group g (warps 4g..4g+3) handles K-stages s ≡ g (mod 2): own smem slots,
// own cp.async groups, own named barrier -> zero cross-group sync in loop.
// Group layout 2x2, warp tile 32x16. Partials combined via smem, then
// group 0 runs the fused exp/andor epilogue.
// ---------------------------------------------------------------------------
__global__ __launch_bounds__(256) void rbf_hmma_kernel(const float* __restrict__ andor,
                                                       float* __restrict__ out) {
    extern __shared__ __align__(16) char smem[];        // SMEM_TOT dynamic
    const uint32_t smem_base = smem_u32(smem);

    const int tid  = threadIdx.x;
    const int wid  = tid >> 5;
    const int lane = tid & 31;
    const int g    = tid >> 7;            // K-group 0/1
    const int gtid = tid & 127;           // thread within group
    const int wl   = wid & 3;             // warp within group
    const int bn0  = blockIdx.x * BN;     // out-tile origin
    const int bm0  = blockIdx.y * BM;     // batch-tile origin
    const int wm   = (wl & 1) * 32;       // warp m offset (2)
    const int wn   = (wl >> 1) * 16;      // warp n offset (2)

    // ---- async load of one K-stage into a group-owned slot (6 x 16B/thread)
    auto load_stage = [&](int slot, int k0) {
        #pragma unroll
        for (int it = 0; it < 6; it++) {
            int idx = gtid + it * 128;        // 0..767
            uint32_t dst;
            const __nv_bfloat16* src;
            if (idx < 512) {                  // A: H rows (compile-time it<4)
                int r = idx >> 3, ch = idx & 7;
                src = g_H + (size_t)(bm0 + r) * K2 + k0 + ch * 8;
                dst = smem_base + slot * STAGE_B + r * ROW_B + ((ch ^ (r & 7)) << 4);
            } else {                          // B: G rows
                int j = idx - 512;
                int r = j >> 3, ch = j & 7;
                src = g_G + (size_t)(bn0 + r) * K2 + k0 + ch * 8;
                dst = smem_base + slot * STAGE_B + A_TILE + r * ROW_B + ((ch ^ (r & 7)) << 4);
            }
            cp_async16(dst, src);
        }
        CP_COMMIT();
    };

    float acc[2][2][4] = {};   // [m16 atom][n8 atom][frag]

    // prologue: stages g and g+2 into group slots 0,1
    load_stage(g * 3 + 0, g * BK);
    load_stage(g * 3 + 1, (g + 2) * BK);

    // ldmatrix lane-address components
    const int a_row = (lane & 7) + ((lane >> 3) & 1) * 8;   // m row within 16
    const int a_ch  = (lane >> 4);                          // logical chunk LSB
    const int b_row = (lane & 7) + ((lane >> 4) << 3);      // n row within 16
    const int b_ch  = ((lane >> 3) & 1);

    int s = g;
    for (int i = 0; i < NITER / 2; i++, s += 2) {
        CP_WAIT(1);                 // own oldest pending group (stage s) done
        BAR_SYNC(1 + g, 128);       // group-wide visibility; slot (i+2)%3 free
        if (s + 4 < NITER) load_stage(g * 3 + (i + 2) % 3, (s + 4) * BK);
        else CP_COMMIT();           // keep CP_WAIT(1) group count exact

        const uint32_t aBase = smem_base + (g * 3 + i % 3) * STAGE_B;
        const uint32_t bBase = aBase + A_TILE;

        #pragma unroll
        for (int kk = 0; kk < 4; kk++) {        // 4 x k16 per stage
            uint32_t a[2][4], b[4];
            #pragma unroll
            for (int im = 0; im < 2; im++) {
                int row = wm + im * 16 + a_row;
                ldsm_x4(a[im][0], a[im][1], a[im][2], a[im][3],
                        aBase + row * ROW_B + (((kk * 2 + a_ch) ^ (row & 7)) << 4));
            }
            {
                int row = wn + b_row;
                ldsm_x4(b[0], b[1], b[2], b[3],
                        bBase + row * ROW_B + (((kk * 2 + b_ch) ^ (row & 7)) << 4));
            }
            #pragma unroll
            for (int im = 0; im < 2; im++)
                #pragma unroll
                for (int in = 0; in < 2; in++)
                    mma16816(acc[im][in], a[im], &b[in * 2]);
        }
    }

    // ---- combine: group 1 parks partials in smem, group 0 reduces + epilogue
    float4* ex = reinterpret_cast<float4*>(smem + EXCH_OFF);
    if (g == 1) {
        #pragma unroll
        for (int im = 0; im < 2; im++)
            #pragma unroll
            for (int in = 0; in < 2; in++)
                ex[gtid * 4 + im * 2 + in] =
                    make_float4(acc[im][in][0], acc[im][in][1], acc[im][in][2], acc[im][in][3]);
    }
    __syncthreads();
    if (g == 0) {
        #pragma unroll
        for (int im = 0; im < 2; im++) {
            const int row0 = bm0 + wm + im * 16 + (lane >> 2);
            #pragma unroll
            for (int in = 0; in < 2; in++) {
                float4 p = ex[gtid * 4 + im * 2 + in];
                float z0 = acc[im][in][0] + p.x;
                float z1 = acc[im][in][1] + p.y;
                float z2 = acc[im][in][2] + p.z;
                float z3 = acc[im][in][3] + p.w;

                const int col = bn0 + wn + in * 8 + (lane & 3) * 2;
                const float c0 = g_c[col],     c1 = g_c[col + 1];
                const float a0 = andor[col],   a1 = andor[col + 1];
                const float m0 = 1.f - 2.f * a0, m1 = 1.f - 2.f * a1;
                float2 r;
                r.x = fmaf(__expf(-(z0 + c0)), m0, a0);
                r.y = fmaf(__expf(-(z1 + c1)), m1, a1);
                *reinterpret_cast<float2*>(&out[(size_t)row0 * OUT_DIM + col]) = r;
                r.x = fmaf(__expf(-(z2 + c0)), m0, a0);
                r.y = fmaf(__expf(-(z3 + c1)), m1, a1);
                *reinterpret_cast<float2*>(&out[(size_t)(row0 + 8) * OUT_DIM + col]) = r;
            }
        }
    }
}

// ---------------------------------------------------------------------------
extern "C" void kernel_launch(void* const* d_in, const int* in_sizes, int n_in,
                              void* d_out, int out_size) {
    const float* x     = (const float*)d_in[0];   // [1024, 1024]
    const float* w     = (const float*)d_in[1];   // [512, 1024]
    const float* u     = (const float*)d_in[2];   // [512, 1024]
    const float* andor = (const float*)d_in[3];   // [1, 512]
    float* out = (float*)d_out;                   // [1024, 512]

    cudaFuncSetAttribute(rbf_hmma_kernel,
                         cudaFuncAttributeMaxDynamicSharedMemorySize, SMEM_TOT);

    prep_all_kernel<<<256 + OUT_DIM, 256>>>(x, w, u);

    dim3 grid(OUT_DIM / BN, BATCH / BM);          // (16, 16) = 256 CTAs
    rbf_hmma_kernel<<<grid, 256, SMEM_TOT>>>(andor, out);
}